// round 2
// baseline (speedup 1.0000x reference)
#include <cuda_runtime.h>

// ---------------------------------------------------------------------------
// HospitalStaffingModel: fused 4-layer MLP + BN-fold + range masking.
// Round 1: exact fp32, packed fma.rn.f32x2 (2 rows per lane-register).
// ---------------------------------------------------------------------------

#define B_TOTAL 131072
#define D_IN    64
#define H1N     512
#define H2N     256
#define NCC     128
#define DCC     128
#define TM      32          // rows per CTA
#define RPAIRS  16          // row pairs per CTA
#define NT      256
#define EPSV    1e-5f
#define NEGV    -1e9f

typedef unsigned long long ull;

__device__ __forceinline__ ull pack2(float lo, float hi) {
    ull r; asm("mov.b64 %0, {%1,%2};" : "=l"(r) : "f"(lo), "f"(hi)); return r;
}
__device__ __forceinline__ void unpack2(ull v, float& lo, float& hi) {
    asm("mov.b64 {%0,%1}, %2;" : "=f"(lo), "=f"(hi) : "l"(v));
}
// Packed dual-fp32 FMA (sm_100+): d = a*b + c on both 32-bit halves.
__device__ __forceinline__ ull ffma2(ull a, ull b, ull c) {
    ull d; asm("fma.rn.f32x2 %0, %1, %2, %3;" : "=l"(d) : "l"(a), "l"(b), "l"(c)); return d;
}
__device__ __forceinline__ ull dup2(float v) { return pack2(v, v); }

// Dynamic SMEM layout (in ull units):
//   [0,      1024)  xs  : [16 rp][64 k]      (phase 0/1)   -- reused as n1s in phase 3
//   [1024,   9216)  h1s : [16 rp][512 c]     (phase 1/2)   -- first 1024 reused as d1s
//   [9216,  13312)  h2s : [16 rp][256 c]     (phase 2/3)
#define SMEM_ULL 13312
#define SMEM_BYTES (SMEM_ULL * 8)

__global__ __launch_bounds__(NT, 2)
void hosp_fused_kernel(
    const float* __restrict__ x,
    const float* __restrict__ W0,  const float* __restrict__ b0,
    const float* __restrict__ g0,  const float* __restrict__ be0,
    const float* __restrict__ rm0, const float* __restrict__ rv0,
    const float* __restrict__ W1,  const float* __restrict__ b1,
    const float* __restrict__ g1,  const float* __restrict__ be1,
    const float* __restrict__ rm1, const float* __restrict__ rv1,
    const float* __restrict__ nW1, const float* __restrict__ nb1,
    const float* __restrict__ nW2, const float* __restrict__ nb2,
    const float* __restrict__ dW1, const float* __restrict__ db1,
    const float* __restrict__ dW2, const float* __restrict__ db2,
    float* __restrict__ out)
{
    extern __shared__ ull sm[];
    ull* xs  = sm;              // [RPAIRS][64]
    ull* h1s = sm + 1024;       // [RPAIRS][512]
    ull* h2s = sm + 9216;       // [RPAIRS][256]
    ull* n1s = sm;              // [RPAIRS][64]  (reuse xs)
    ull* d1s = sm + 1024;       // [RPAIRS][64]  (reuse h1s head)

    __shared__ int sn[TM];
    __shared__ int sd[TM];

    const int tid = threadIdx.x;
    const int r0  = blockIdx.x * TM;

    // ---------------- Phase 0: load x tile (row-pair packed) + masks --------
    for (int i = tid; i < TM * D_IN; i += NT) {
        const int row = i >> 6;
        const int k   = i & 63;
        const float v = x[(size_t)(r0 + row) * D_IN + k];
        reinterpret_cast<float*>(xs)[(((row >> 1) * 64 + k) << 1) + (row & 1)] = v;
    }
    if (tid < TM) {
        sn[tid] = (int)x[(size_t)(r0 + tid) * D_IN + 60];   // column -4
    } else if (tid < 2 * TM) {
        const int r = tid - TM;
        sd[r] = (int)x[(size_t)(r0 + r) * D_IN + 61];       // column -3
    }
    __syncthreads();

    // ---------------- Phase 1: h1 = relu(bn0(x @ W0 + b0))  [32 x 512] ------
    {
        const int cg  = tid & 127;        // 4 cols each: [4cg, 4cg+4)
        const int rpb = (tid >> 7) * 8;   // 8 row-pairs
        const int c4  = cg << 2;

        ull acc[8][4];
        #pragma unroll
        for (int r = 0; r < 8; r++)
            #pragma unroll
            for (int c = 0; c < 4; c++) acc[r][c] = 0ULL;

        #pragma unroll 2
        for (int k = 0; k < D_IN; k++) {
            const float4 w = *reinterpret_cast<const float4*>(W0 + (size_t)k * H1N + c4);
            const ull w0 = dup2(w.x), w1 = dup2(w.y), w2 = dup2(w.z), w3 = dup2(w.w);
            #pragma unroll
            for (int r = 0; r < 8; r++) {
                const ull p = xs[(rpb + r) * 64 + k];
                acc[r][0] = ffma2(p, w0, acc[r][0]);
                acc[r][1] = ffma2(p, w1, acc[r][1]);
                acc[r][2] = ffma2(p, w2, acc[r][2]);
                acc[r][3] = ffma2(p, w3, acc[r][3]);
            }
        }
        #pragma unroll
        for (int c = 0; c < 4; c++) {
            const int j = c4 + c;
            const float s  = g0[j] * rsqrtf(rv0[j] + EPSV);
            const float bb = (b0[j] - rm0[j]) * s + be0[j];
            #pragma unroll
            for (int r = 0; r < 8; r++) {
                float lo, hi; unpack2(acc[r][c], lo, hi);
                lo = fmaxf(fmaf(lo, s, bb), 0.0f);
                hi = fmaxf(fmaf(hi, s, bb), 0.0f);
                h1s[(rpb + r) * H1N + j] = pack2(lo, hi);
            }
        }
    }
    __syncthreads();

    // ---------------- Phase 2: h2 = relu(bn1(h1 @ W1 + b1)) [32 x 256] ------
    {
        const int cg  = tid & 63;         // 4 cols each of 256
        const int rpb = (tid >> 6) * 4;   // 4 row-pairs
        const int c4  = cg << 2;

        ull acc[4][4];
        #pragma unroll
        for (int r = 0; r < 4; r++)
            #pragma unroll
            for (int c = 0; c < 4; c++) acc[r][c] = 0ULL;

        #pragma unroll 4
        for (int k = 0; k < H1N; k++) {
            const float4 w = *reinterpret_cast<const float4*>(W1 + (size_t)k * H2N + c4);
            const ull w0 = dup2(w.x), w1 = dup2(w.y), w2 = dup2(w.z), w3 = dup2(w.w);
            #pragma unroll
            for (int r = 0; r < 4; r++) {
                const ull p = h1s[(rpb + r) * H1N + k];
                acc[r][0] = ffma2(p, w0, acc[r][0]);
                acc[r][1] = ffma2(p, w1, acc[r][1]);
                acc[r][2] = ffma2(p, w2, acc[r][2]);
                acc[r][3] = ffma2(p, w3, acc[r][3]);
            }
        }
        #pragma unroll
        for (int c = 0; c < 4; c++) {
            const int j = c4 + c;
            const float s  = g1[j] * rsqrtf(rv1[j] + EPSV);
            const float bb = (b1[j] - rm1[j]) * s + be1[j];
            #pragma unroll
            for (int r = 0; r < 4; r++) {
                float lo, hi; unpack2(acc[r][c], lo, hi);
                lo = fmaxf(fmaf(lo, s, bb), 0.0f);
                hi = fmaxf(fmaf(hi, s, bb), 0.0f);
                h2s[(rpb + r) * H2N + j] = pack2(lo, hi);
            }
        }
    }
    __syncthreads();

    // ---------------- Phase 3a: n1/d1 = relu(h2 @ {n,d}W1 + b) [32 x 64] ----
    {
        const int cg = tid & 15;          // 4 cols each of 64
        const int rp = tid >> 4;          // one row-pair (16 total)
        const int c4 = cg << 2;

        ull na[4], da[4];
        #pragma unroll
        for (int c = 0; c < 4; c++) { na[c] = 0ULL; da[c] = 0ULL; }

        #pragma unroll 4
        for (int k = 0; k < H2N; k++) {
            const float4 wn = *reinterpret_cast<const float4*>(nW1 + (size_t)k * 64 + c4);
            const float4 wd = *reinterpret_cast<const float4*>(dW1 + (size_t)k * 64 + c4);
            const ull p = h2s[rp * H2N + k];
            na[0] = ffma2(p, dup2(wn.x), na[0]);
            na[1] = ffma2(p, dup2(wn.y), na[1]);
            na[2] = ffma2(p, dup2(wn.z), na[2]);
            na[3] = ffma2(p, dup2(wn.w), na[3]);
            da[0] = ffma2(p, dup2(wd.x), da[0]);
            da[1] = ffma2(p, dup2(wd.y), da[1]);
            da[2] = ffma2(p, dup2(wd.z), da[2]);
            da[3] = ffma2(p, dup2(wd.w), da[3]);
        }
        __syncthreads();   // everyone done reading h2s/xs before we overwrite n1s/d1s
        #pragma unroll
        for (int c = 0; c < 4; c++) {
            const int j = c4 + c;
            const float bn_ = nb1[j];
            const float bd_ = db1[j];
            float lo, hi;
            unpack2(na[c], lo, hi);
            n1s[rp * 64 + j] = pack2(fmaxf(lo + bn_, 0.0f), fmaxf(hi + bn_, 0.0f));
            unpack2(da[c], lo, hi);
            d1s[rp * 64 + j] = pack2(fmaxf(lo + bd_, 0.0f), fmaxf(hi + bd_, 0.0f));
        }
    }
    __syncthreads();

    // ---------------- Phase 3b: logits + bias + range mask + store ----------
    {
        const int cg  = tid & 31;         // 4 cols each of 128
        const int rpb = (tid >> 5) * 2;   // 2 row-pairs
        const int c4  = cg << 2;

        ull na[2][4], da[2][4];
        #pragma unroll
        for (int r = 0; r < 2; r++)
            #pragma unroll
            for (int c = 0; c < 4; c++) { na[r][c] = 0ULL; da[r][c] = 0ULL; }

        #pragma unroll 4
        for (int k = 0; k < 64; k++) {
            const float4 wn = *reinterpret_cast<const float4*>(nW2 + (size_t)k * NCC + c4);
            const float4 wd = *reinterpret_cast<const float4*>(dW2 + (size_t)k * DCC + c4);
            const ull wn0 = dup2(wn.x), wn1 = dup2(wn.y), wn2 = dup2(wn.z), wn3 = dup2(wn.w);
            const ull wd0 = dup2(wd.x), wd1 = dup2(wd.y), wd2 = dup2(wd.z), wd3 = dup2(wd.w);
            #pragma unroll
            for (int r = 0; r < 2; r++) {
                const ull pn = n1s[(rpb + r) * 64 + k];
                const ull pd = d1s[(rpb + r) * 64 + k];
                na[r][0] = ffma2(pn, wn0, na[r][0]);
                na[r][1] = ffma2(pn, wn1, na[r][1]);
                na[r][2] = ffma2(pn, wn2, na[r][2]);
                na[r][3] = ffma2(pn, wn3, na[r][3]);
                da[r][0] = ffma2(pd, wd0, da[r][0]);
                da[r][1] = ffma2(pd, wd1, da[r][1]);
                da[r][2] = ffma2(pd, wd2, da[r][2]);
                da[r][3] = ffma2(pd, wd3, da[r][3]);
            }
        }

        float bn_[4], bd_[4];
        #pragma unroll
        for (int c = 0; c < 4; c++) { bn_[c] = nb2[c4 + c]; bd_[c] = db2[c4 + c]; }

        float* outN = out;
        float* outD = out + (size_t)B_TOTAL * NCC;

        #pragma unroll
        for (int r = 0; r < 2; r++) {
            const int rp = rpb + r;
            const int rowE = 2 * rp;      // even row of the pair
            const int rowO = rowE + 1;
            const int snE = sn[rowE], snO = sn[rowO];
            const int sdE = sd[rowE], sdO = sd[rowO];

            float4 oNE, oNO, oDE, oDO;
            float* pNE = &oNE.x; float* pNO = &oNO.x;
            float* pDE = &oDE.x; float* pDO = &oDO.x;

            #pragma unroll
            for (int c = 0; c < 4; c++) {
                const int j = c4 + c;
                float lo, hi;
                unpack2(na[r][c], lo, hi);
                pNE[c] = (j <= snE) ? (lo + bn_[c]) : NEGV;
                pNO[c] = (j <= snO) ? (hi + bn_[c]) : NEGV;
                unpack2(da[r][c], lo, hi);
                pDE[c] = (j <= sdE) ? (lo + bd_[c]) : NEGV;
                pDO[c] = (j <= sdO) ? (hi + bd_[c]) : NEGV;
            }
            const size_t gRowE = (size_t)(r0 + rowE);
            const size_t gRowO = (size_t)(r0 + rowO);
            *reinterpret_cast<float4*>(outN + gRowE * NCC + c4) = oNE;
            *reinterpret_cast<float4*>(outN + gRowO * NCC + c4) = oNO;
            *reinterpret_cast<float4*>(outD + gRowE * DCC + c4) = oDE;
            *reinterpret_cast<float4*>(outD + gRowO * DCC + c4) = oDO;
        }
    }
}

extern "C" void kernel_launch(void* const* d_in, const int* in_sizes, int n_in,
                              void* d_out, int out_size)
{
    const float* x   = (const float*)d_in[0];
    const float* W0  = (const float*)d_in[1];
    const float* b0  = (const float*)d_in[2];
    const float* g0  = (const float*)d_in[3];
    const float* be0 = (const float*)d_in[4];
    const float* rm0 = (const float*)d_in[5];
    const float* rv0 = (const float*)d_in[6];
    const float* W1  = (const float*)d_in[7];
    const float* b1  = (const float*)d_in[8];
    const float* g1  = (const float*)d_in[9];
    const float* be1 = (const float*)d_in[10];
    const float* rm1 = (const float*)d_in[11];
    const float* rv1 = (const float*)d_in[12];
    const float* nW1 = (const float*)d_in[13];
    const float* nb1 = (const float*)d_in[14];
    const float* nW2 = (const float*)d_in[15];
    const float* nb2 = (const float*)d_in[16];
    const float* dW1 = (const float*)d_in[17];
    const float* db1 = (const float*)d_in[18];
    const float* dW2 = (const float*)d_in[19];
    const float* db2 = (const float*)d_in[20];

    cudaFuncSetAttribute(hosp_fused_kernel,
                         cudaFuncAttributeMaxDynamicSharedMemorySize, SMEM_BYTES);

    const int grid = B_TOTAL / TM;   // 4096
    hosp_fused_kernel<<<grid, NT, SMEM_BYTES>>>(
        x, W0, b0, g0, be0, rm0, rv0,
        W1, b1, g1, be1, rm1, rv1,
        nW1, nb1, nW2, nb2, dW1, db1, dW2, db2,
        (float*)d_out);
}

// round 4
// speedup vs baseline: 4.1328x; 4.1328x over previous
#include <cuda_runtime.h>
#include <cuda_bf16.h>
#include <cstdint>

// ============================================================================
// HospitalStaffingModel via warp-level bf16 mma.sync (m16n8k16) on sm_103.
//   L0: x[64,64]   @ W0[64,512]   -> BN+ReLU -> h1 bf16 (SMEM)
//   L1: h1[64,512] @ W1[512,256]  -> BN+ReLU -> h2     (W1 cp.async-streamed)
//   H : h2[64,256] @ [nW1|dW1][256,128] -> +b,ReLU -> a3
//   F : a3[64,128] @ blockdiag(nW2,dW2)[128,256] -> +b, range mask -> out
// Weights prepacked into B-fragment-ready bf16 images (one LDS.64 per MMA).
// ============================================================================

typedef unsigned long long ull;
#define B_TOTAL 131072
#define EPSV    1e-5f
#define NEGV    -1e9f

// ---- prepacked weight fragment buffer (ull entries) -------------------------
// entry layout per ks,nt: [lane 0..31] ull = {reg0(lo u32), reg1(hi u32)}
#define GW0 0u        // W0: 4 ks x 64 nt  -> 8192
#define GW1 8192u     // W1: 32 ks x 32 nt -> 32768
#define GWH 40960u    // [nW1|dW1]: 16 ks x 16 nt -> 8192
#define GWF 49152u    // blockdiag(nW2,dW2): 4 ks x 32 nt -> 4096
#define GTOT 53248u

__device__ __align__(1024) ull g_wfrag[GTOT];

// ---- SMEM layout (byte offsets) ---------------------------------------------
#define SO_CS    0        // 1920 f32 consts (7680 B)
#define SO_SN    7680     // 64 int
#define SO_SD    7936     // 64 int
#define SO_XS    8192     // x   bf16x2: [64][36] u32   (9216 B)
#define SO_H1    17408    // h1  bf16x2: [64][260] u32  (66560 B) ; also Wf + stage
#define SO_H2    83968    // h2  bf16x2: [64][132] u32  (33792 B)
#define SO_A3    117760   // a3  bf16x2: [64][68]  u32  (17408 B)
#define SO_WSL   135168   // weight slice: 2 x 4096 ull (65536 B)
#define SMEM_BYTES 200704

// ---- helpers -----------------------------------------------------------------
__device__ __forceinline__ uint32_t smem_u32(const void* p) {
    uint32_t a;
    asm("{ .reg .u64 t; cvta.to.shared.u64 t, %1; cvt.u32.u64 %0, t; }" : "=r"(a) : "l"(p));
    return a;
}
__device__ __forceinline__ uint32_t pack_bf16x2(float lo, float hi) {
    uint32_t r;
    asm("cvt.rn.bf16x2.f32 %0, %1, %2;" : "=r"(r) : "f"(hi), "f"(lo));
    return r;
}
__device__ __forceinline__ void cp_async16(uint32_t sdst, const void* gsrc) {
    asm volatile("cp.async.cg.shared.global [%0], [%1], 16;" :: "r"(sdst), "l"(gsrc) : "memory");
}
#define CP_COMMIT() asm volatile("cp.async.commit_group;" ::: "memory")
#define CP_WAIT(n)  asm volatile("cp.async.wait_group %0;" :: "n"(n) : "memory")

__device__ __forceinline__ void mma16816(float* c, const uint32_t* a, uint32_t b0, uint32_t b1) {
    asm volatile(
        "mma.sync.aligned.m16n8k16.row.col.f32.bf16.bf16.f32 "
        "{%0,%1,%2,%3}, {%4,%5,%6,%7}, {%8,%9}, {%0,%1,%2,%3};"
        : "+f"(c[0]), "+f"(c[1]), "+f"(c[2]), "+f"(c[3])
        : "r"(a[0]), "r"(a[1]), "r"(a[2]), "r"(a[3]), "r"(b0), "r"(b1));
}

// Generic register-tiled block: C[2][NT][4] += A(act)[rows R0..R0+31] x Wfrag
// act: u32 bf16x2 buffer, row stride SA (u32), k-pair base kpb (u32 index)
template<int KS, int NT>
__device__ __forceinline__ void gemm_block(
    const uint32_t* __restrict__ act, int SA, int kpb,
    const ull* __restrict__ wf, int NTW, int ntb,
    int R0, int lane, float* C)
{
    const int g = lane >> 2, t = lane & 3;
    #pragma unroll
    for (int ks = 0; ks < KS; ks++) {
        uint32_t a[2][4];
        const int kp = kpb + ks * 8 + t;
        #pragma unroll
        for (int mt = 0; mt < 2; mt++) {
            const int r = R0 + mt * 16 + g;
            a[mt][0] = act[r * SA + kp];
            a[mt][1] = act[(r + 8) * SA + kp];
            a[mt][2] = act[r * SA + kp + 4];
            a[mt][3] = act[(r + 8) * SA + kp + 4];
        }
        #pragma unroll
        for (int nt = 0; nt < NT; nt++) {
            const ull b = wf[(size_t)(ks * NTW + ntb + nt) * 32 + lane];
            const uint32_t b0 = (uint32_t)b, b1 = (uint32_t)(b >> 32);
            #pragma unroll
            for (int mt = 0; mt < 2; mt++)
                mma16816(C + (mt * NT + nt) * 4, a[mt], b0, b1);
        }
    }
}

// ============================================================================
// Prepack: bake B-fragment-ready bf16 weight images.
//   reg0 = {W[k0][n], W[k0+1][n]}, reg1 = {W[k0+8][n], W[k0+9][n]}
//   k0 = ks*16 + (lane&3)*2, n = nt*8 + (lane>>2)
// ============================================================================
__global__ void hosp_prepack(const float* __restrict__ W0, const float* __restrict__ W1,
                             const float* __restrict__ nW1, const float* __restrict__ dW1,
                             const float* __restrict__ nW2, const float* __restrict__ dW2)
{
    const int idx = blockIdx.x * 256 + threadIdx.x;
    if (idx >= (int)GTOT) return;
    const int lane = idx & 31;
    const int tg = lane & 3, gg = lane >> 2;
    float f0, f1, f2, f3;

    if (idx < 8192) {                       // W0 [64K x 512N]
        const int gidx = idx >> 5;
        const int ks = gidx >> 6, nt = gidx & 63;
        const int k0 = ks * 16 + tg * 2, n = nt * 8 + gg;
        f0 = W0[(k0    ) * 512 + n]; f1 = W0[(k0 + 1) * 512 + n];
        f2 = W0[(k0 + 8) * 512 + n]; f3 = W0[(k0 + 9) * 512 + n];
    } else if (idx < 40960) {               // W1 [512K x 256N]
        const int gidx = (idx - 8192) >> 5;
        const int ks = gidx >> 5, nt = gidx & 31;
        const int k0 = ks * 16 + tg * 2, n = nt * 8 + gg;
        f0 = W1[(size_t)(k0    ) * 256 + n]; f1 = W1[(size_t)(k0 + 1) * 256 + n];
        f2 = W1[(size_t)(k0 + 8) * 256 + n]; f3 = W1[(size_t)(k0 + 9) * 256 + n];
    } else if (idx < 49152) {               // [nW1|dW1] [256K x 128N]
        const int gidx = (idx - 40960) >> 5;
        const int ks = gidx >> 4, nt = gidx & 15;
        const int k0 = ks * 16 + tg * 2, n = nt * 8 + gg;
        const float* W = (n < 64) ? nW1 : dW1;
        const int nn = n & 63;
        f0 = W[(k0    ) * 64 + nn]; f1 = W[(k0 + 1) * 64 + nn];
        f2 = W[(k0 + 8) * 64 + nn]; f3 = W[(k0 + 9) * 64 + nn];
    } else {                                // blockdiag(nW2,dW2) [64K x 256N]
        const int gidx = (idx - 49152) >> 5;
        const int ks = gidx >> 5, nt = gidx & 31;
        const int k0 = ks * 16 + tg * 2;
        const float* W = (nt < 16) ? nW2 : dW2;
        const int n = ((nt & 15) * 8 + gg);
        f0 = W[(k0    ) * 128 + n]; f1 = W[(k0 + 1) * 128 + n];
        f2 = W[(k0 + 8) * 128 + n]; f3 = W[(k0 + 9) * 128 + n];
    }
    const uint32_t r0 = pack_bf16x2(f0, f1);
    const uint32_t r1 = pack_bf16x2(f2, f3);
    g_wfrag[idx] = (ull)r0 | ((ull)r1 << 32);
}

// ============================================================================
// Main kernel: 64 rows/CTA, 256 threads (8 warps = 2 Mwarps x 4 Nwarps).
// ============================================================================
__global__ __launch_bounds__(256, 1)
void hosp_hmma_kernel(
    const float* __restrict__ x,
    const float* __restrict__ b0,  const float* __restrict__ g0,
    const float* __restrict__ be0, const float* __restrict__ rm0, const float* __restrict__ rv0,
    const float* __restrict__ b1,  const float* __restrict__ g1,
    const float* __restrict__ be1, const float* __restrict__ rm1, const float* __restrict__ rv1,
    const float* __restrict__ nb1, const float* __restrict__ nb2,
    const float* __restrict__ db1, const float* __restrict__ db2,
    float* __restrict__ out)
{
    extern __shared__ unsigned char smem[];
    float*    cs  = reinterpret_cast<float*>(smem + SO_CS);
    int*      sns = reinterpret_cast<int*>(smem + SO_SN);
    int*      sds = reinterpret_cast<int*>(smem + SO_SD);
    uint32_t* xs  = reinterpret_cast<uint32_t*>(smem + SO_XS);
    uint32_t* h1  = reinterpret_cast<uint32_t*>(smem + SO_H1);
    uint32_t* h2  = reinterpret_cast<uint32_t*>(smem + SO_H2);
    uint32_t* a3  = reinterpret_cast<uint32_t*>(smem + SO_A3);
    ull*      wsl = reinterpret_cast<ull*>(smem + SO_WSL);
    const uint32_t wsl_b = smem_u32(wsl);

    const int tid  = threadIdx.x;
    const int lane = tid & 31;
    const int wid  = tid >> 5;
    const int mw   = wid & 1;          // M-warp (rows 32*mw .. +32)
    const int nw   = wid >> 1;         // N-warp (0..3)
    const int R0   = mw * 32;
    const int g    = lane >> 2, t = lane & 3;
    const int r0   = blockIdx.x * 64;

    // ---- prologue: async W0 -> wsl (64 KB) ----------------------------------
    {
        const char* src = reinterpret_cast<const char*>(g_wfrag + GW0);
        for (int i = tid; i < 4096; i += 256)
            cp_async16(wsl_b + i * 16, src + i * 16);
        CP_COMMIT();
    }
    // ---- fold BN consts + biases --------------------------------------------
    for (int i = tid; i < 512; i += 256) {
        const float s = g0[i] * rsqrtf(rv0[i] + EPSV);
        cs[i] = s; cs[512 + i] = (b0[i] - rm0[i]) * s + be0[i];
    }
    if (tid < 256) {
        const int i = tid;
        const float s = g1[i] * rsqrtf(rv1[i] + EPSV);
        cs[1024 + i] = s; cs[1280 + i] = (b1[i] - rm1[i]) * s + be1[i];
    }
    if (tid < 64) { cs[1536 + tid] = nb1[tid]; cs[1600 + tid] = db1[tid]; }
    if (tid < 128) { cs[1664 + tid] = nb2[tid]; cs[1792 + tid] = db2[tid]; }

    // ---- x tile: fp32 -> bf16x2, [64][36] ------------------------------------
    {
        const float2* x2 = reinterpret_cast<const float2*>(x + (size_t)r0 * 64);
        for (int i = tid; i < 2048; i += 256) {
            const int row = i >> 5, kp = i & 31;
            const float2 v = x2[row * 32 + kp];
            xs[row * 36 + kp] = pack_bf16x2(v.x, v.y);
        }
        if (tid < 64)       sns[tid] = (int)x[(size_t)(r0 + tid) * 64 + 60];
        else if (tid < 128) sds[tid - 64] = (int)x[(size_t)(r0 + tid - 64) * 64 + 61];
    }
    CP_WAIT(0);
    __syncthreads();

    // ================= L0: two N-halves of 8 n-tiles each =====================
    #pragma unroll 1
    for (int half = 0; half < 2; half++) {
        float C[64];
        #pragma unroll
        for (int i = 0; i < 64; i++) C[i] = 0.0f;
        const int ntb = nw * 16 + half * 8;
        gemm_block<4, 8>(xs, 36, 0, wsl, 64, ntb, R0, lane, C);
        #pragma unroll
        for (int mt = 0; mt < 2; mt++)
            #pragma unroll
            for (int nt = 0; nt < 8; nt++) {
                const float* c = C + (mt * 8 + nt) * 4;
                const int j = (ntb + nt) * 8 + t * 2;
                const int rA = R0 + mt * 16 + g, rB = rA + 8;
                const float v0 = fmaxf(fmaf(c[0], cs[j],     cs[512 + j]),     0.0f);
                const float v1 = fmaxf(fmaf(c[1], cs[j + 1], cs[512 + j + 1]), 0.0f);
                const float v2 = fmaxf(fmaf(c[2], cs[j],     cs[512 + j]),     0.0f);
                const float v3 = fmaxf(fmaf(c[3], cs[j + 1], cs[512 + j + 1]), 0.0f);
                h1[rA * 260 + (j >> 1)] = pack_bf16x2(v0, v1);
                h1[rB * 260 + (j >> 1)] = pack_bf16x2(v2, v3);
            }
    }
    __syncthreads();   // h1 complete; wsl free

    // ================= L1: K=512, 8 double-buffered 32KB chunks ===============
    {
        float C[64];
        #pragma unroll
        for (int i = 0; i < 64; i++) C[i] = 0.0f;
        // preload chunk 0
        {
            const char* src = reinterpret_cast<const char*>(g_wfrag + GW1);
            for (int i = tid; i < 2048; i += 256)
                cp_async16(wsl_b + i * 16, src + i * 16);
            CP_COMMIT();
        }
        #pragma unroll 1
        for (int e = 0; e < 8; e++) {
            if (e < 7) {
                const char* src = reinterpret_cast<const char*>(g_wfrag + GW1 + (size_t)(e + 1) * 4096);
                const uint32_t dst = wsl_b + ((e + 1) & 1) * 32768;
                for (int i = tid; i < 2048; i += 256)
                    cp_async16(dst + i * 16, src + i * 16);
                CP_COMMIT();
                CP_WAIT(1);
            } else {
                CP_WAIT(0);
            }
            __syncthreads();
            gemm_block<4, 8>(h1, 260, e * 32, wsl + (e & 1) * 4096, 32, nw * 8, R0, lane, C);
            __syncthreads();
        }
        // epilogue L1 -> h2
        #pragma unroll
        for (int mt = 0; mt < 2; mt++)
            #pragma unroll
            for (int nt = 0; nt < 8; nt++) {
                const float* c = C + (mt * 8 + nt) * 4;
                const int j = (nw * 8 + nt) * 8 + t * 2;
                const int rA = R0 + mt * 16 + g, rB = rA + 8;
                const float v0 = fmaxf(fmaf(c[0], cs[1024 + j],     cs[1280 + j]),     0.0f);
                const float v1 = fmaxf(fmaf(c[1], cs[1024 + j + 1], cs[1280 + j + 1]), 0.0f);
                const float v2 = fmaxf(fmaf(c[2], cs[1024 + j],     cs[1280 + j]),     0.0f);
                const float v3 = fmaxf(fmaf(c[3], cs[1024 + j + 1], cs[1280 + j + 1]), 0.0f);
                h2[rA * 132 + (j >> 1)] = pack_bf16x2(v0, v1);
                h2[rB * 132 + (j >> 1)] = pack_bf16x2(v2, v3);
            }
    }
    __syncthreads();   // h2 complete; wsl free; h1 dead

    // ---- async: heads weights -> wsl (64 KB), final weights -> h1 region -----
    {
        const char* srcH = reinterpret_cast<const char*>(g_wfrag + GWH);
        for (int i = tid; i < 4096; i += 256)
            cp_async16(wsl_b + i * 16, srcH + i * 16);
        CP_COMMIT();
        const char* srcF = reinterpret_cast<const char*>(g_wfrag + GWF);
        const uint32_t dstF = smem_u32(smem + SO_H1);
        for (int i = tid; i < 2048; i += 256)
            cp_async16(dstF + i * 16, srcF + i * 16);
        CP_COMMIT();
    }
    CP_WAIT(1);        // heads weights ready (final may still be in flight)
    __syncthreads();

    // ================= Heads: h2 @ [nW1|dW1] -> a3 ============================
    {
        float C[32];
        #pragma unroll
        for (int i = 0; i < 32; i++) C[i] = 0.0f;
        gemm_block<16, 4>(h2, 132, 0, wsl, 16, nw * 4, R0, lane, C);
        #pragma unroll
        for (int mt = 0; mt < 2; mt++)
            #pragma unroll
            for (int nt = 0; nt < 4; nt++) {
                const float* c = C + (mt * 4 + nt) * 4;
                const int j = (nw * 4 + nt) * 8 + t * 2;
                const int rA = R0 + mt * 16 + g, rB = rA + 8;
                const float v0 = fmaxf(c[0] + cs[1536 + j],     0.0f);
                const float v1 = fmaxf(c[1] + cs[1536 + j + 1], 0.0f);
                const float v2 = fmaxf(c[2] + cs[1536 + j],     0.0f);
                const float v3 = fmaxf(c[3] + cs[1536 + j + 1], 0.0f);
                a3[rA * 68 + (j >> 1)] = pack_bf16x2(v0, v1);
                a3[rB * 68 + (j >> 1)] = pack_bf16x2(v2, v3);
            }
    }
    CP_WAIT(0);        // final weights ready
    __syncthreads();

    // ================= Final: a3 @ blockdiag -> logits ========================
    {
        float C[64];
        #pragma unroll
        for (int i = 0; i < 64; i++) C[i] = 0.0f;
        const int ntb = nw * 8;                       // global nt 0..31
        const int kpb = (ntb >= 16) ? 32 : 0;         // doctor uses a3 cols 64..127
        const ull* wf = reinterpret_cast<const ull*>(smem + SO_H1);
        gemm_block<4, 8>(a3, 68, kpb, wf, 32, ntb, R0, lane, C);
        __syncthreads();                              // all reads of Wf done

        float* stage = reinterpret_cast<float*>(smem + SO_H1);  // [64][260] f32
        #pragma unroll
        for (int mt = 0; mt < 2; mt++)
            #pragma unroll
            for (int nt = 0; nt < 8; nt++) {
                const float* c = C + (mt * 8 + nt) * 4;
                const int jg = (ntb + nt) * 8 + t * 2;     // 0..255
                const int head = jg >> 7, col = jg & 127;
                const int rA = R0 + mt * 16 + g, rB = rA + 8;
                const int smA = head ? sds[rA] : sns[rA];
                const int smB = head ? sds[rB] : sns[rB];
                const float bb0 = cs[1664 + jg], bb1 = cs[1664 + jg + 1];
                stage[rA * 260 + jg]     = (col     <= smA) ? (c[0] + bb0) : NEGV;
                stage[rA * 260 + jg + 1] = (col + 1 <= smA) ? (c[1] + bb1) : NEGV;
                stage[rB * 260 + jg]     = (col     <= smB) ? (c[2] + bb0) : NEGV;
                stage[rB * 260 + jg + 1] = (col + 1 <= smB) ? (c[3] + bb1) : NEGV;
            }
        __syncthreads();

        // coalesced copy-out: nurse = stage cols [0,128), doctor = [128,256)
        const uint4* st4 = reinterpret_cast<const uint4*>(stage);
        uint4* outN4 = reinterpret_cast<uint4*>(out) + (size_t)r0 * 32;
        uint4* outD4 = reinterpret_cast<uint4*>(out + (size_t)B_TOTAL * 128) + (size_t)r0 * 32;
        for (int i = tid; i < 4096; i += 256) {
            const int hd  = i >> 11;
            const int tt  = i & 2047;
            const int row = tt >> 5, q = tt & 31;
            const uint4 v = st4[row * 65 + hd * 32 + q];
            (hd ? outD4 : outN4)[row * 32 + q] = v;
        }
    }
}

extern "C" void kernel_launch(void* const* d_in, const int* in_sizes, int n_in,
                              void* d_out, int out_size)
{
    const float* x   = (const float*)d_in[0];
    const float* W0  = (const float*)d_in[1];
    const float* b0  = (const float*)d_in[2];
    const float* g0  = (const float*)d_in[3];
    const float* be0 = (const float*)d_in[4];
    const float* rm0 = (const float*)d_in[5];
    const float* rv0 = (const float*)d_in[6];
    const float* W1  = (const float*)d_in[7];
    const float* b1  = (const float*)d_in[8];
    const float* g1  = (const float*)d_in[9];
    const float* be1 = (const float*)d_in[10];
    const float* rm1 = (const float*)d_in[11];
    const float* rv1 = (const float*)d_in[12];
    const float* nW1 = (const float*)d_in[13];
    const float* nb1 = (const float*)d_in[14];
    const float* nW2 = (const float*)d_in[15];
    const float* nb2 = (const float*)d_in[16];
    const float* dW1 = (const float*)d_in[17];
    const float* db1 = (const float*)d_in[18];
    const float* dW2 = (const float*)d_in[19];
    const float* db2 = (const float*)d_in[20];

    cudaFuncSetAttribute(hosp_hmma_kernel,
                         cudaFuncAttributeMaxDynamicSharedMemorySize, SMEM_BYTES);

    hosp_prepack<<<208, 256>>>(W0, W1, nW1, dW1, nW2, dW2);
    hosp_hmma_kernel<<<B_TOTAL / 64, 256, SMEM_BYTES>>>(
        x, b0, g0, be0, rm0, rv0, b1, g1, be1, rm1, rv1,
        nb1, nb2, db1, db2, (float*)d_out);
}